// round 14
// baseline (speedup 1.0000x reference)
#include <cuda_runtime.h>
#include <cuda_fp16.h>
#include <cstdint>

// ---------------- scratch (__device__ globals; no allocation) ----------------
// layout: [img][ocGroup 0..3][px 0..1023][8 words of 16 fp16 ch]
__device__ uint32_t g_a32[1024 * 32768];   // conv1 output (134MB)
__device__ float g_pool[1024 * 128];       // pooled conv2 features

// ---------------- helpers ----------------
__device__ __forceinline__ uint32_t smem_u32(const void* p) {
    uint32_t a;
    asm("{ .reg .u64 t; cvta.to.shared.u64 t, %1; cvt.u32.u64 %0, t; }" : "=r"(a) : "l"(p));
    return a;
}
__device__ __forceinline__ uint32_t pack_h2(float a, float b) {
    __half2 t = __floats2half2_rn(a, b);
    return *reinterpret_cast<uint32_t*>(&t);
}
__device__ __forceinline__ void ldmx4(uint32_t& r0, uint32_t& r1, uint32_t& r2, uint32_t& r3,
                                      uint32_t addr) {
    asm volatile("ldmatrix.sync.aligned.m8n8.x4.shared.b16 {%0,%1,%2,%3}, [%4];"
                 : "=r"(r0), "=r"(r1), "=r"(r2), "=r"(r3) : "r"(addr));
}
__device__ __forceinline__ void mma16816(float* c, const uint32_t* a, uint32_t b0, uint32_t b1) {
    asm volatile(
        "mma.sync.aligned.m16n8k16.row.col.f32.f16.f16.f32 "
        "{%0,%1,%2,%3}, {%4,%5,%6,%7}, {%8,%9}, {%0,%1,%2,%3};"
        : "+f"(c[0]), "+f"(c[1]), "+f"(c[2]), "+f"(c[3])
        : "r"(a[0]), "r"(a[1]), "r"(a[2]), "r"(a[3]), "r"(b0), "r"(b1));
}
__device__ __forceinline__ void half_bar(int barid) {
    asm volatile("bar.sync %0, %1;" :: "r"(barid), "r"(256) : "memory");
}

// ---------------- conv1 via mma.sync: im2col GEMM (M=1024px, N=64, K=27->32) ----------
// SMEM (bytes): sIn f32 12288 | A 1024x20w = 81920 | B 64x20w = 5120 | bias 256
static constexpr int C1_SIN = 0;
static constexpr int C1_A = 12288;
static constexpr int C1_B = 94208;
static constexpr int C1_BIAS = 99328;
static constexpr int C1M_SMEM = 99584;

__global__ __launch_bounds__(256) void conv1_mma_kernel(const float* __restrict__ x,
                                                        const float* __restrict__ w,
                                                        const float* __restrict__ bias) {
    extern __shared__ __align__(16) char smem[];
    uint32_t sbase = smem_u32(smem);
    float* sIn = reinterpret_cast<float*>(smem + C1_SIN);
    uint32_t* sA32 = reinterpret_cast<uint32_t*>(smem + C1_A);
    uint32_t* sB32 = reinterpret_cast<uint32_t*>(smem + C1_B);
    float* sBias = reinterpret_cast<float*>(smem + C1_BIAS);
    int img = blockIdx.x, tid = threadIdx.x, lane = tid & 31, wid = tid >> 5;

    for (int j = tid; j < 3072; j += 256) sIn[j] = x[img * 3072 + j];
    // B: sB[n][k] fp16 pairs, k = ic*9 + ky*3 + kx, padded K 27->32, row stride 20 words
    for (int e = tid; e < 1024; e += 256) {
        int n = e >> 4, kk = e & 15;
        int k0 = 2 * kk, k1 = k0 + 1;
        float h0 = (k0 < 27) ? w[n * 27 + k0] : 0.f;
        float h1 = (k1 < 27) ? w[n * 27 + k1] : 0.f;
        sB32[n * 20 + kk] = pack_h2(h0, h1);
    }
    if (tid < 64) sBias[tid] = bias[tid];
    __syncthreads();

    // build A (im2col): thread owns fixed kk; px = (tid>>4) + i*16
    {
        int kk = tid & 15, t4 = tid >> 4;
        int k0 = 2 * kk, k1 = k0 + 1;
        int ic0 = k0 / 9, s0 = k0 - 9 * ic0, dy0 = s0 / 3 - 1, dx0 = s0 % 3 - 1;
        int ic1 = k1 / 9, s1 = k1 - 9 * ic1, dy1 = s1 / 3 - 1, dx1 = s1 % 3 - 1;
        bool ok0 = k0 < 27, ok1 = k1 < 27;
#pragma unroll 4
        for (int i = 0; i < 64; i++) {
            int px = t4 + i * 16;
            int r = px >> 5, xc = px & 31;
            float v0 = 0.f, v1 = 0.f;
            if (ok0) {
                int y = r + dy0, xx = xc + dx0;
                if ((unsigned)y < 32u && (unsigned)xx < 32u) v0 = sIn[ic0 * 1024 + y * 32 + xx];
            }
            if (ok1) {
                int y = r + dy1, xx = xc + dx1;
                if ((unsigned)y < 32u && (unsigned)xx < 32u) v1 = sIn[ic1 * 1024 + y * 32 + xx];
            }
            sA32[px * 20 + kk] = pack_h2(v0, v1);
        }
    }
    __syncthreads();

    // GEMM: warp w -> px [w*128, w*128+128), all 64 oc
    uint32_t aThr = sbase + C1_A + (uint32_t)((lane & 15) * 80 + (lane >> 4) * 16);
    uint32_t bThr = sbase + C1_B +
                    (uint32_t)((((lane >> 4) * 8 + (lane & 7)) * 40 + ((lane >> 3) & 1) * 8) * 2);
    uint32_t bfr[4][2][4];
#pragma unroll
    for (int j2 = 0; j2 < 4; j2++)
#pragma unroll
        for (int ks = 0; ks < 2; ks++)
            ldmx4(bfr[j2][ks][0], bfr[j2][ks][1], bfr[j2][ks][2], bfr[j2][ks][3],
                  bThr + (uint32_t)(j2 * 1280 + ks * 32));

    uint32_t* gdst = g_a32 + (size_t)img * 32768;
#pragma unroll
    for (int f = 0; f < 8; f++) {
        int px_m = wid * 128 + f * 16;
        uint32_t a[2][4];
        ldmx4(a[0][0], a[0][1], a[0][2], a[0][3], aThr + (uint32_t)(px_m * 80));
        ldmx4(a[1][0], a[1][1], a[1][2], a[1][3], aThr + (uint32_t)(px_m * 80 + 32));
        float acc[8][4];
#pragma unroll
        for (int j = 0; j < 8; j++)
#pragma unroll
            for (int q = 0; q < 4; q++) acc[j][q] = 0.f;
#pragma unroll
        for (int ks = 0; ks < 2; ks++)
#pragma unroll
            for (int j2 = 0; j2 < 4; j2++) {
                mma16816(acc[j2 * 2], a[ks], bfr[j2][ks][0], bfr[j2][ks][1]);
                mma16816(acc[j2 * 2 + 1], a[ks], bfr[j2][ks][2], bfr[j2][ks][3]);
            }
        int pr = px_m + (lane >> 2);
#pragma unroll
        for (int j = 0; j < 8; j++) {
            int c0 = j * 8 + 2 * (lane & 3);
            float b0 = sBias[c0], b1 = sBias[c0 + 1];
            uint32_t* dst = gdst + (j >> 1) * 8192;
            int word = (j & 1) * 4 + (lane & 3);
            dst[pr * 8 + word] = pack_h2(fmaxf(acc[j][0] + b0, 0.f),
                                         fmaxf(acc[j][1] + b1, 0.f));
            dst[(pr + 8) * 8 + word] = pack_h2(fmaxf(acc[j][2] + b0, 0.f),
                                               fmaxf(acc[j][3] + b1, 0.f));
        }
    }
}

// ---------------- conv2: two images in flight (2 halves x 8 warps), named barriers ----
// SMEM: B 149504 | 2 half-bufs (6 rows x 34 px x 144B = 29376) | bias 512 | pool 4096
static constexpr int B_OFF = 0;
static constexpr int ABUF_OFF = 149504;
static constexpr int ABUF_SZ = 29376;
static constexpr int SBIAS_OFF = 208256;
static constexpr int SPOOL_OFF = 208768;   // 16 warps x 64 floats
static constexpr int SMEM2_TOTAL = 212864;

__global__ __launch_bounds__(512, 1) void conv2_mma_kernel(const float* __restrict__ w,
                                                           const float* __restrict__ bias) {
    extern __shared__ __align__(16) char smem[];
    uint32_t sbase = smem_u32(smem);
    float* sBias = reinterpret_cast<float*>(smem + SBIAS_OFF);
    float* sPool = reinterpret_cast<float*>(smem + SPOOL_OFF);
    int tid = threadIdx.x, lane = tid & 31, wid = tid >> 5;
    int h = tid >> 8, ltid = tid & 255;
    int lwid = wid & 7;
    int m_idx = lwid & 3, n_idx = lwid >> 2;  // per half: 4 m-warps (32px) x 2 n-warps (64oc)
    int barid = h + 1;

    for (int e = tid; e < 864; e += 512) {
        int b = e / 432, rem = e % 432;
        int rr = rem / 72, rem2 = rem % 72;
        int side = rem2 / 36, q = rem2 % 36;
        *reinterpret_cast<uint32_t*>(smem + ABUF_OFF + b * ABUF_SZ + rr * 4896 +
                                     (side ? 33 : 0) * 144 + q * 4) = 0u;
    }
    for (int e = tid; e < 73728; e += 512) {
        int n = e / 576, k = e - n * 576;
        int ic = k & 63, s = k >> 6;
        float v = w[n * 576 + ic * 9 + s];
        *reinterpret_cast<__half*>(smem + B_OFF + (n * 584 + k) * 2) = __float2half(v);
    }
    if (tid < 128) sBias[tid] = bias[tid];
    __syncthreads();

    uint32_t aThr = (uint32_t)((lane & 15) * 144 + ((lane >> 4) & 1) * 16);
    uint32_t bThr = (uint32_t)(((((lane >> 4) & 1) * 8 + (lane & 7)) * 584 +
                                ((lane >> 3) & 1) * 8) * 2 + n_idx * 74752);
    uint32_t abuf = sbase + ABUF_OFF + (uint32_t)(h * ABUF_SZ);

    int K = (1024 - blockIdx.x + 147) / 148;
    int kmid = (K + 1) >> 1;
    int kbeg = h ? kmid : 0;
    int kend = h ? K : kmid;

    for (int kk = kbeg; kk < kend; kk++) {
        int img = blockIdx.x + 148 * kk;
        const uint32_t* gsrc = g_a32 + (size_t)img * 32768;
        float pool[8][2];
#pragma unroll
        for (int j = 0; j < 8; j++) { pool[j][0] = 0.f; pool[j][1] = 0.f; }

        for (int t = 0; t < 8; t++) {
            half_bar(barid);
#pragma unroll
            for (int i = 0; i < 6; i++) {
                int c = ltid + i * 256;
                int wr = c >> 8, rem = c & 255;
                int px = rem >> 3, g = (rem >> 1) & 3, q = rem & 1;
                int gy = t * 4 + wr - 1;
                uint32_t ok = ((unsigned)gy < 32u) ? 16u : 0u;
                int gyc = gy < 0 ? 0 : (gy > 31 ? 31 : gy);
                const void* gp = gsrc + g * 8192 + (gyc * 32 + px) * 8 + q * 4;
                uint32_t sd = abuf + (uint32_t)(wr * 4896 + (px + 1) * 144 + g * 32 + q * 16);
                asm volatile("cp.async.cg.shared.global [%0], [%1], 16, %2;"
                             :: "r"(sd), "l"(gp), "r"(ok) : "memory");
            }
            asm volatile("cp.async.commit_group;" ::: "memory");
            asm volatile("cp.async.wait_group 0;" ::: "memory");
            half_bar(barid);

            float acc[2][8][4];
#pragma unroll
            for (int f = 0; f < 2; f++)
#pragma unroll
                for (int j = 0; j < 8; j++)
#pragma unroll
                    for (int q = 0; q < 4; q++) acc[f][j][q] = 0.f;

            uint32_t aBase = abuf + (uint32_t)(m_idx * 4896) + aThr;
            uint32_t bBase = sbase + B_OFF + bThr;
#pragma unroll
            for (int s = 0; s < 9; s++) {
                const uint32_t doff = (uint32_t)((s / 3) * 4896 + (s % 3) * 144);
#pragma unroll
                for (int ks = 0; ks < 4; ks++) {
                    uint32_t a[2][4];
#pragma unroll
                    for (int f = 0; f < 2; f++)
                        ldmx4(a[f][0], a[f][1], a[f][2], a[f][3],
                              aBase + doff + (uint32_t)(f * 2304 + ks * 32));
                    uint32_t kofs = (uint32_t)(s * 128 + ks * 32);
#pragma unroll
                    for (int fp = 0; fp < 4; fp++) {
                        uint32_t r0, r1, r2, r3;
                        ldmx4(r0, r1, r2, r3, bBase + (uint32_t)(fp * 18688) + kofs);
#pragma unroll
                        for (int f = 0; f < 2; f++) {
                            mma16816(acc[f][fp * 2], a[f], r0, r1);
                            mma16816(acc[f][fp * 2 + 1], a[f], r2, r3);
                        }
                    }
                }
            }
#pragma unroll
            for (int j = 0; j < 8; j++) {
                float b0 = sBias[n_idx * 64 + j * 8 + (lane & 3) * 2];
                float b1 = sBias[n_idx * 64 + j * 8 + (lane & 3) * 2 + 1];
                pool[j][0] += fmaxf(acc[0][j][0] + b0, 0.f) + fmaxf(acc[0][j][2] + b0, 0.f) +
                              fmaxf(acc[1][j][0] + b0, 0.f) + fmaxf(acc[1][j][2] + b0, 0.f);
                pool[j][1] += fmaxf(acc[0][j][1] + b1, 0.f) + fmaxf(acc[0][j][3] + b1, 0.f) +
                              fmaxf(acc[1][j][1] + b1, 0.f) + fmaxf(acc[1][j][3] + b1, 0.f);
            }
        }
#pragma unroll
        for (int off = 4; off <= 16; off <<= 1)
#pragma unroll
            for (int j = 0; j < 8; j++) {
                pool[j][0] += __shfl_xor_sync(0xffffffffu, pool[j][0], off);
                pool[j][1] += __shfl_xor_sync(0xffffffffu, pool[j][1], off);
            }
        if (lane < 4) {
            float* sp = sPool + wid * 64;
#pragma unroll
            for (int j = 0; j < 8; j++) {
                sp[j * 8 + lane * 2] = pool[j][0];
                sp[j * 8 + lane * 2 + 1] = pool[j][1];
            }
        }
        half_bar(barid);
        if (ltid < 128) {
            int ni = ltid >> 6, col = ltid & 63;
            float s = 0.f;
#pragma unroll
            for (int m = 0; m < 4; m++) s += sPool[(h * 8 + ni * 4 + m) * 64 + col];
            g_pool[img * 128 + ni * 64 + col] = s * (1.f / 1024.f);
        }
    }
}

// ---------------- fused tail: fc + mask + colsum + sage1 + colsum + sage2 ----------------
static constexpr int TP_POOL = 0;       // 32 x 128
static constexpr int TP_H    = 4096;    // 32 x 256 (reused as sage2 partials)
static constexpr int TP_O1   = 12288;   // 32 x 256
static constexpr int TP_CS   = 20480;   // 256
static constexpr int TP_B2   = 20736;   // 256
static constexpr int TP_MASK = 20992;   // 32
static constexpr int TAIL_SMEM = 21024 * 4;

__global__ __launch_bounds__(256) void tail_kernel(
    const float* __restrict__ fc_w, const float* __restrict__ fc_b,
    const float* __restrict__ mask,
    const float* __restrict__ s1_lw, const float* __restrict__ s1_lb,
    const float* __restrict__ s1_rw,
    const float* __restrict__ s2_lw, const float* __restrict__ s2_lb,
    const float* __restrict__ s2_rw,
    float* __restrict__ out) {
    extern __shared__ float sm[];
    float* sPool = sm + TP_POOL;
    float* sH    = sm + TP_H;
    float* sO1   = sm + TP_O1;
    float* sCs   = sm + TP_CS;
    float* sB2   = sm + TP_B2;
    float* sMask = sm + TP_MASK;
    int b = blockIdx.x, tid = threadIdx.x;

    for (int e = tid; e < 4096; e += 256) sPool[e] = g_pool[b * 4096 + e];
    if (tid < 32) sMask[tid] = mask[b * 32 + tid];
    __syncthreads();

    {
        float acc[32];
#pragma unroll
        for (int n = 0; n < 32; n++) acc[n] = 0.f;
        const float4* wrow = reinterpret_cast<const float4*>(fc_w + tid * 128);
#pragma unroll 4
        for (int k4 = 0; k4 < 32; k4++) {
            float4 wv = wrow[k4];
#pragma unroll
            for (int n = 0; n < 32; n++) {
                float4 hv = *reinterpret_cast<const float4*>(sPool + n * 128 + k4 * 4);
                acc[n] += wv.x * hv.x + wv.y * hv.y + wv.z * hv.z + wv.w * hv.w;
            }
        }
        float fb = fc_b[tid];
#pragma unroll
        for (int n = 0; n < 32; n++) sH[n * 256 + tid] = (acc[n] + fb) * sMask[n];
    }
    __syncthreads();
    {
        float s = 0.f;
#pragma unroll
        for (int n = 0; n < 32; n++) s += sH[n * 256 + tid];
        sCs[tid] = s;
    }
    __syncthreads();

    {
        float acc[32];
#pragma unroll
        for (int n = 0; n < 32; n++) acc[n] = 0.f;
        float bacc = 0.f;
        const float4* lw4 = reinterpret_cast<const float4*>(s1_lw + tid * 256);
        const float4* rw4 = reinterpret_cast<const float4*>(s1_rw + tid * 256);
#pragma unroll 2
        for (int k4 = 0; k4 < 64; k4++) {
            float4 lw = lw4[k4], rw = rw4[k4];
            float4 cs = *reinterpret_cast<const float4*>(sCs + k4 * 4);
            bacc += cs.x * lw.x + cs.y * lw.y + cs.z * lw.z + cs.w * lw.w;
            float4 wc;
            wc.x = rw.x - lw.x * (1.f / 31.f); wc.y = rw.y - lw.y * (1.f / 31.f);
            wc.z = rw.z - lw.z * (1.f / 31.f); wc.w = rw.w - lw.w * (1.f / 31.f);
#pragma unroll
            for (int n = 0; n < 32; n++) {
                float4 hv = *reinterpret_cast<const float4*>(sH + n * 256 + k4 * 4);
                acc[n] += wc.x * hv.x + wc.y * hv.y + wc.z * hv.z + wc.w * hv.w;
            }
        }
        float base = s1_lb[tid] + bacc * (1.f / 31.f);
#pragma unroll
        for (int n = 0; n < 32; n++) sO1[n * 256 + tid] = fmaxf(base + acc[n], 0.f);
    }
    __syncthreads();
    {
        float s = 0.f;
#pragma unroll
        for (int n = 0; n < 32; n++) s += sO1[n * 256 + tid];
        sCs[tid] = s;
    }
    __syncthreads();

    {
        int o2 = tid & 127, half = tid >> 7;
        float acc[32];
#pragma unroll
        for (int n = 0; n < 32; n++) acc[n] = 0.f;
        float bacc = 0.f;
        const float4* lw4 = reinterpret_cast<const float4*>(s2_lw + o2 * 256 + half * 128);
        const float4* rw4 = reinterpret_cast<const float4*>(s2_rw + o2 * 256 + half * 128);
        const float* csb = sCs + half * 128;
        const float* o1b = sO1 + half * 128;
#pragma unroll 2
        for (int k4 = 0; k4 < 32; k4++) {
            float4 lw = lw4[k4], rw = rw4[k4];
            float4 cs = *reinterpret_cast<const float4*>(csb + k4 * 4);
            bacc += cs.x * lw.x + cs.y * lw.y + cs.z * lw.z + cs.w * lw.w;
            float4 wc;
            wc.x = rw.x - lw.x * (1.f / 31.f); wc.y = rw.y - lw.y * (1.f / 31.f);
            wc.z = rw.z - lw.z * (1.f / 31.f); wc.w = rw.w - lw.w * (1.f / 31.f);
#pragma unroll
            for (int n = 0; n < 32; n++) {
                float4 hv = *reinterpret_cast<const float4*>(o1b + n * 256 + k4 * 4);
                acc[n] += wc.x * hv.x + wc.y * hv.y + wc.z * hv.z + wc.w * hv.w;
            }
        }
#pragma unroll
        for (int n = 0; n < 32; n++) sH[n * 256 + tid] = acc[n];
        sB2[tid] = bacc;
    }
    __syncthreads();
    for (int e = tid; e < 4096; e += 256) {
        int n = e >> 7, o2 = e & 127;
        float v = sH[n * 256 + o2] + sH[n * 256 + o2 + 128];
        float base = s2_lb[o2] + (sB2[o2] + sB2[o2 + 128]) * (1.f / 31.f);
        out[(b * 32 + n) * 128 + o2] = base + v;
    }
}

// ---------------- launch ----------------
extern "C" void kernel_launch(void* const* d_in, const int* in_sizes, int n_in,
                              void* d_out, int out_size) {
    const float* x       = (const float*)d_in[0];
    const float* mask    = (const float*)d_in[1];
    const float* conv1_w = (const float*)d_in[2];
    const float* conv1_b = (const float*)d_in[3];
    const float* conv2_w = (const float*)d_in[4];
    const float* conv2_b = (const float*)d_in[5];
    const float* fc_w    = (const float*)d_in[6];
    const float* fc_b    = (const float*)d_in[7];
    const float* s1_lw   = (const float*)d_in[8];
    const float* s1_lb   = (const float*)d_in[9];
    const float* s1_rw   = (const float*)d_in[10];
    const float* s2_lw   = (const float*)d_in[11];
    const float* s2_lb   = (const float*)d_in[12];
    const float* s2_rw   = (const float*)d_in[13];
    float* out = (float*)d_out;

    cudaFuncSetAttribute(conv1_mma_kernel, cudaFuncAttributeMaxDynamicSharedMemorySize,
                         C1M_SMEM);
    cudaFuncSetAttribute(conv2_mma_kernel, cudaFuncAttributeMaxDynamicSharedMemorySize,
                         SMEM2_TOTAL);
    cudaFuncSetAttribute(tail_kernel, cudaFuncAttributeMaxDynamicSharedMemorySize, TAIL_SMEM);

    conv1_mma_kernel<<<1024, 256, C1M_SMEM>>>(x, conv1_w, conv1_b);
    conv2_mma_kernel<<<148, 512, SMEM2_TOTAL>>>(conv2_w, conv2_b);
    tail_kernel<<<32, 256, TAIL_SMEM>>>(fc_w, fc_b, mask, s1_lw, s1_lb, s1_rw,
                                        s2_lw, s2_lb, s2_rw, out);
}

// round 15
// speedup vs baseline: 1.1335x; 1.1335x over previous
#include <cuda_runtime.h>
#include <cuda_fp16.h>
#include <cstdint>

// ---------------- scratch (__device__ globals; no allocation) ----------------
__device__ float g_pool[1024 * 128];       // pooled conv2 features

// ---------------- helpers ----------------
__device__ __forceinline__ uint32_t smem_u32(const void* p) {
    uint32_t a;
    asm("{ .reg .u64 t; cvta.to.shared.u64 t, %1; cvt.u32.u64 %0, t; }" : "=r"(a) : "l"(p));
    return a;
}
__device__ __forceinline__ uint32_t pack_h2(float a, float b) {
    __half2 t = __floats2half2_rn(a, b);
    return *reinterpret_cast<uint32_t*>(&t);
}
__device__ __forceinline__ void ldmx4(uint32_t& r0, uint32_t& r1, uint32_t& r2, uint32_t& r3,
                                      uint32_t addr) {
    asm volatile("ldmatrix.sync.aligned.m8n8.x4.shared.b16 {%0,%1,%2,%3}, [%4];"
                 : "=r"(r0), "=r"(r1), "=r"(r2), "=r"(r3) : "r"(addr));
}
__device__ __forceinline__ void mma16816(float* c, const uint32_t* a, uint32_t b0, uint32_t b1) {
    asm volatile(
        "mma.sync.aligned.m16n8k16.row.col.f32.f16.f16.f32 "
        "{%0,%1,%2,%3}, {%4,%5,%6,%7}, {%8,%9}, {%0,%1,%2,%3};"
        : "+f"(c[0]), "+f"(c[1]), "+f"(c[2]), "+f"(c[3])
        : "r"(a[0]), "r"(a[1]), "r"(a[2]), "r"(a[3]), "r"(b0), "r"(b1));
}
__device__ __forceinline__ void half_bar(int barid) {
    asm volatile("bar.sync %0, %1;" :: "r"(barid), "r"(256) : "memory");
}

// ---------------- fused conv1+conv2+pool kernel ----------------
// SMEM (bytes):
//   B (conv2 weights fp16, padded k-stride 584)            0 .. 149504
//   A-bufs: 2 halves x (6 rows x 34 px x 144B = 29376)     149504 .. 208256
//   conv2 bias (128 f32)                                   208256 .. 208768
//   pool (16 warps x 64 f32)                               208768 .. 212864
//   conv1 weights (27 kt x 32 half2 words)                 212864 .. 216320
//   conv1 bias (32 half2 words, padded)                    216320 .. 216576
//   input imgs fp16: 2 halves x (3 x 1024 half = 6144)     216576 .. 228864
static constexpr int B_OFF = 0;
static constexpr int ABUF_OFF = 149504;
static constexpr int ABUF_SZ = 29376;
static constexpr int SBIAS_OFF = 208256;
static constexpr int SPOOL_OFF = 208768;
static constexpr int C1W_OFF = 212864;
static constexpr int C1B_OFF = 216320;
static constexpr int SINH_OFF = 216576;
static constexpr int SMEM2_TOTAL = 228864;

__global__ __launch_bounds__(512, 1) void conv_fused_kernel(
    const float* __restrict__ x,
    const float* __restrict__ c1w, const float* __restrict__ c1b,
    const float* __restrict__ w, const float* __restrict__ bias) {
    extern __shared__ __align__(16) char smem[];
    uint32_t sbase = smem_u32(smem);
    float* sBias = reinterpret_cast<float*>(smem + SBIAS_OFF);
    float* sPool = reinterpret_cast<float*>(smem + SPOOL_OFF);
    __half2* c1wW = reinterpret_cast<__half2*>(smem + C1W_OFF);
    __half2* c1b2 = reinterpret_cast<__half2*>(smem + C1B_OFF);
    int tid = threadIdx.x, lane = tid & 31, wid = tid >> 5;
    int h = tid >> 8, ltid = tid & 255;
    int lwid = wid & 7;
    int m_idx = lwid & 3, n_idx = lwid >> 2;  // per half: 4 m-warps (32px) x 2 n-warps (64oc)
    int barid = h + 1;

    // zero x-halo pixels (px cols 0, 33) of both half-buffers, 6 rows each
    for (int e = tid; e < 864; e += 512) {
        int b = e / 432, rem = e % 432;
        int rr = rem / 72, rem2 = rem % 72;
        int side = rem2 / 36, q = rem2 % 36;
        *reinterpret_cast<uint32_t*>(smem + ABUF_OFF + b * ABUF_SZ + rr * 4896 +
                                     (side ? 33 : 0) * 144 + q * 4) = 0u;
    }
    // conv2 B: sB[n][k], k = s*64 + ic, k-stride padded to 584 elems (fp16)
    for (int e = tid; e < 73728; e += 512) {
        int n = e / 576, k = e - n * 576;
        int ic = k & 63, s = k >> 6;
        float v = w[n * 576 + ic * 9 + s];
        *reinterpret_cast<__half*>(smem + B_OFF + (n * 584 + k) * 2) = __float2half(v);
    }
    // conv1 weights: [kt][word w] where word w = oc pair (2w, 2w+1)
    for (int e = tid; e < 864; e += 512) {
        int kt = e >> 5, wdx = e & 31;
        c1wW[kt * 32 + wdx] = __floats2half2_rn(c1w[(2 * wdx) * 27 + kt],
                                                c1w[(2 * wdx + 1) * 27 + kt]);
    }
    if (tid < 32) c1b2[tid] = __floats2half2_rn(c1b[2 * tid], c1b[2 * tid + 1]);
    if (tid < 128) sBias[tid] = bias[tid];
    __syncthreads();

    // per-thread ldmatrix address components (conv2)
    uint32_t aThr = (uint32_t)((lane & 15) * 144 + ((lane >> 4) & 1) * 16);
    uint32_t bThr = (uint32_t)(((((lane >> 4) & 1) * 8 + (lane & 7)) * 584 +
                                ((lane >> 3) & 1) * 8) * 2 + n_idx * 74752);
    uint32_t abuf = sbase + ABUF_OFF + (uint32_t)(h * ABUF_SZ);
    char* abufp = smem + ABUF_OFF + h * ABUF_SZ;
    const __half* sI = reinterpret_cast<const __half*>(smem + SINH_OFF + h * 6144);
    uint32_t* sInW = reinterpret_cast<uint32_t*>(smem + SINH_OFF + h * 6144);

    // conv1-band thread mapping (fixed per thread)
    int c1_r0 = ltid >> 7;            // 0/1: warps 0-3 rows {0,2,4}, warps 4-7 rows {1,3,5}
    int c1_ocg = (ltid >> 5) & 3;
    int c1_px = ltid & 31;

    // image split between halves
    int K = (1024 - blockIdx.x + 147) / 148;
    int kmid = (K + 1) >> 1;
    int kbeg = h ? kmid : 0;
    int kend = h ? K : kmid;

    for (int kk = kbeg; kk < kend; kk++) {
        int img = blockIdx.x + 148 * kk;
        // load this half's input image fp32 -> fp16 SMEM
        {
            const float4* gx4 = reinterpret_cast<const float4*>(x + (size_t)img * 3072);
#pragma unroll
            for (int i = 0; i < 3; i++) {
                int e = ltid + i * 256;
                float4 v = gx4[e];
                sInW[2 * e] = pack_h2(v.x, v.y);
                sInW[2 * e + 1] = pack_h2(v.z, v.w);
            }
        }
        float pool[8][2];
#pragma unroll
        for (int j = 0; j < 8; j++) { pool[j][0] = 0.f; pool[j][1] = 0.f; }

        for (int t = 0; t < 8; t++) {
            half_bar(barid);   // prev tile's A reads done; input stores visible
            // ---- conv1 band: rows gy = 4t-1 .. 4t+4 -> A-buffer (fp16, HFMA2) ----
            {
                __half2 z2 = __float2half2_rn(0.f);
                __half2 acc[3][8];
#pragma unroll
                for (int j = 0; j < 8; j++) {
                    __half2 b = c1b2[c1_ocg * 8 + j];
#pragma unroll
                    for (int i = 0; i < 3; i++) acc[i][j] = b;
                }
#pragma unroll
                for (int ic = 0; ic < 3; ic++) {
#pragma unroll
                    for (int ky = 0; ky < 3; ky++) {
                        __half2 iv[3][3];
#pragma unroll
                        for (int i = 0; i < 3; i++) {
                            int y = 4 * t + c1_r0 + 2 * i + ky - 2;
#pragma unroll
                            for (int dx = 0; dx < 3; dx++) {
                                int xx = c1_px + dx - 1;
                                __half v = __float2half(0.f);
                                if ((unsigned)y < 32u && (unsigned)xx < 32u)
                                    v = sI[ic * 1024 + y * 32 + xx];
                                iv[i][dx] = __half2half2(v);
                            }
                        }
#pragma unroll
                        for (int kx = 0; kx < 3; kx++) {
                            int kt = ic * 9 + ky * 3 + kx;
                            const __half2* wp = c1wW + kt * 32 + c1_ocg * 8;
                            __half2 w8[8];
#pragma unroll
                            for (int j = 0; j < 8; j++) w8[j] = wp[j];
#pragma unroll
                            for (int i = 0; i < 3; i++)
#pragma unroll
                                for (int j = 0; j < 8; j++)
                                    acc[i][j] = __hfma2(iv[i][kx], w8[j], acc[i][j]);
                        }
                    }
                }
#pragma unroll
                for (int i = 0; i < 3; i++) {
                    int row = c1_r0 + 2 * i;
                    int gy = 4 * t + row - 1;
                    char* ap = abufp + row * 4896 + (c1_px + 1) * 144 + c1_ocg * 32;
                    uint4 v0, v1;
                    if ((unsigned)gy < 32u) {
                        __half2 o[8];
#pragma unroll
                        for (int j = 0; j < 8; j++) o[j] = __hmax2(acc[i][j], z2);
                        v0 = *reinterpret_cast<uint4*>(&o[0]);
                        v1 = *reinterpret_cast<uint4*>(&o[4]);
                    } else {
                        v0 = make_uint4(0u, 0u, 0u, 0u);
                        v1 = v0;
                    }
                    *reinterpret_cast<uint4*>(ap) = v0;
                    *reinterpret_cast<uint4*>(ap + 16) = v1;
                }
            }
            half_bar(barid);   // A-buffer visible to whole half

            // ---- conv2 MMA ----
            float acc[2][8][4];
#pragma unroll
            for (int f = 0; f < 2; f++)
#pragma unroll
                for (int j = 0; j < 8; j++)
#pragma unroll
                    for (int q = 0; q < 4; q++) acc[f][j][q] = 0.f;

            uint32_t aBase = abuf + (uint32_t)(m_idx * 4896) + aThr;
            uint32_t bBase = sbase + B_OFF + bThr;
#pragma unroll
            for (int s = 0; s < 9; s++) {
                const uint32_t doff = (uint32_t)((s / 3) * 4896 + (s % 3) * 144);
#pragma unroll
                for (int ks = 0; ks < 4; ks++) {
                    uint32_t a[2][4];
#pragma unroll
                    for (int f = 0; f < 2; f++)
                        ldmx4(a[f][0], a[f][1], a[f][2], a[f][3],
                              aBase + doff + (uint32_t)(f * 2304 + ks * 32));
                    uint32_t kofs = (uint32_t)(s * 128 + ks * 32);
#pragma unroll
                    for (int fp = 0; fp < 4; fp++) {
                        uint32_t r0, r1, r2, r3;
                        ldmx4(r0, r1, r2, r3, bBase + (uint32_t)(fp * 18688) + kofs);
#pragma unroll
                        for (int f = 0; f < 2; f++) {
                            mma16816(acc[f][fp * 2], a[f], r0, r1);
                            mma16816(acc[f][fp * 2 + 1], a[f], r2, r3);
                        }
                    }
                }
            }
            // bias + relu + pixel-pool
#pragma unroll
            for (int j = 0; j < 8; j++) {
                float b0 = sBias[n_idx * 64 + j * 8 + (lane & 3) * 2];
                float b1 = sBias[n_idx * 64 + j * 8 + (lane & 3) * 2 + 1];
                pool[j][0] += fmaxf(acc[0][j][0] + b0, 0.f) + fmaxf(acc[0][j][2] + b0, 0.f) +
                              fmaxf(acc[1][j][0] + b0, 0.f) + fmaxf(acc[1][j][2] + b0, 0.f);
                pool[j][1] += fmaxf(acc[0][j][1] + b1, 0.f) + fmaxf(acc[0][j][3] + b1, 0.f) +
                              fmaxf(acc[1][j][1] + b1, 0.f) + fmaxf(acc[1][j][3] + b1, 0.f);
            }
        }
        // reduce over lanes with same (lane&3)
#pragma unroll
        for (int off = 4; off <= 16; off <<= 1)
#pragma unroll
            for (int j = 0; j < 8; j++) {
                pool[j][0] += __shfl_xor_sync(0xffffffffu, pool[j][0], off);
                pool[j][1] += __shfl_xor_sync(0xffffffffu, pool[j][1], off);
            }
        if (lane < 4) {
            float* sp = sPool + wid * 64;
#pragma unroll
            for (int j = 0; j < 8; j++) {
                sp[j * 8 + lane * 2] = pool[j][0];
                sp[j * 8 + lane * 2 + 1] = pool[j][1];
            }
        }
        half_bar(barid);
        if (ltid < 128) {
            int ni = ltid >> 6, col = ltid & 63;
            float s = 0.f;
#pragma unroll
            for (int m = 0; m < 4; m++) s += sPool[(h * 8 + ni * 4 + m) * 64 + col];
            g_pool[img * 128 + ni * 64 + col] = s * (1.f / 1024.f);
        }
    }
}

// ---------------- fused tail: fc + mask + colsum + sage1 + colsum + sage2 ----------------
static constexpr int TP_POOL = 0;       // 32 x 128
static constexpr int TP_H    = 4096;    // 32 x 256 (reused as sage2 partials)
static constexpr int TP_O1   = 12288;   // 32 x 256
static constexpr int TP_CS   = 20480;   // 256
static constexpr int TP_B2   = 20736;   // 256
static constexpr int TP_MASK = 20992;   // 32
static constexpr int TAIL_SMEM = 21024 * 4;

__global__ __launch_bounds__(256) void tail_kernel(
    const float* __restrict__ fc_w, const float* __restrict__ fc_b,
    const float* __restrict__ mask,
    const float* __restrict__ s1_lw, const float* __restrict__ s1_lb,
    const float* __restrict__ s1_rw,
    const float* __restrict__ s2_lw, const float* __restrict__ s2_lb,
    const float* __restrict__ s2_rw,
    float* __restrict__ out) {
    extern __shared__ float sm[];
    float* sPool = sm + TP_POOL;
    float* sH    = sm + TP_H;
    float* sO1   = sm + TP_O1;
    float* sCs   = sm + TP_CS;
    float* sB2   = sm + TP_B2;
    float* sMask = sm + TP_MASK;
    int b = blockIdx.x, tid = threadIdx.x;

    for (int e = tid; e < 4096; e += 256) sPool[e] = g_pool[b * 4096 + e];
    if (tid < 32) sMask[tid] = mask[b * 32 + tid];
    __syncthreads();

    {
        float acc[32];
#pragma unroll
        for (int n = 0; n < 32; n++) acc[n] = 0.f;
        const float4* wrow = reinterpret_cast<const float4*>(fc_w + tid * 128);
#pragma unroll 4
        for (int k4 = 0; k4 < 32; k4++) {
            float4 wv = wrow[k4];
#pragma unroll
            for (int n = 0; n < 32; n++) {
                float4 hv = *reinterpret_cast<const float4*>(sPool + n * 128 + k4 * 4);
                acc[n] += wv.x * hv.x + wv.y * hv.y + wv.z * hv.z + wv.w * hv.w;
            }
        }
        float fb = fc_b[tid];
#pragma unroll
        for (int n = 0; n < 32; n++) sH[n * 256 + tid] = (acc[n] + fb) * sMask[n];
    }
    __syncthreads();
    {
        float s = 0.f;
#pragma unroll
        for (int n = 0; n < 32; n++) s += sH[n * 256 + tid];
        sCs[tid] = s;
    }
    __syncthreads();

    {
        float acc[32];
#pragma unroll
        for (int n = 0; n < 32; n++) acc[n] = 0.f;
        float bacc = 0.f;
        const float4* lw4 = reinterpret_cast<const float4*>(s1_lw + tid * 256);
        const float4* rw4 = reinterpret_cast<const float4*>(s1_rw + tid * 256);
#pragma unroll 2
        for (int k4 = 0; k4 < 64; k4++) {
            float4 lw = lw4[k4], rw = rw4[k4];
            float4 cs = *reinterpret_cast<const float4*>(sCs + k4 * 4);
            bacc += cs.x * lw.x + cs.y * lw.y + cs.z * lw.z + cs.w * lw.w;
            float4 wc;
            wc.x = rw.x - lw.x * (1.f / 31.f); wc.y = rw.y - lw.y * (1.f / 31.f);
            wc.z = rw.z - lw.z * (1.f / 31.f); wc.w = rw.w - lw.w * (1.f / 31.f);
#pragma unroll
            for (int n = 0; n < 32; n++) {
                float4 hv = *reinterpret_cast<const float4*>(sH + n * 256 + k4 * 4);
                acc[n] += wc.x * hv.x + wc.y * hv.y + wc.z * hv.z + wc.w * hv.w;
            }
        }
        float base = s1_lb[tid] + bacc * (1.f / 31.f);
#pragma unroll
        for (int n = 0; n < 32; n++) sO1[n * 256 + tid] = fmaxf(base + acc[n], 0.f);
    }
    __syncthreads();
    {
        float s = 0.f;
#pragma unroll
        for (int n = 0; n < 32; n++) s += sO1[n * 256 + tid];
        sCs[tid] = s;
    }
    __syncthreads();

    {
        int o2 = tid & 127, half = tid >> 7;
        float acc[32];
#pragma unroll
        for (int n = 0; n < 32; n++) acc[n] = 0.f;
        float bacc = 0.f;
        const float4* lw4 = reinterpret_cast<const float4*>(s2_lw + o2 * 256 + half * 128);
        const float4* rw4 = reinterpret_cast<const float4*>(s2_rw + o2 * 256 + half * 128);
        const float* csb = sCs + half * 128;
        const float* o1b = sO1 + half * 128;
#pragma unroll 2
        for (int k4 = 0; k4 < 32; k4++) {
            float4 lw = lw4[k4], rw = rw4[k4];
            float4 cs = *reinterpret_cast<const float4*>(csb + k4 * 4);
            bacc += cs.x * lw.x + cs.y * lw.y + cs.z * lw.z + cs.w * lw.w;
            float4 wc;
            wc.x = rw.x - lw.x * (1.f / 31.f); wc.y = rw.y - lw.y * (1.f / 31.f);
            wc.z = rw.z - lw.z * (1.f / 31.f); wc.w = rw.w - lw.w * (1.f / 31.f);
#pragma unroll
            for (int n = 0; n < 32; n++) {
                float4 hv = *reinterpret_cast<const float4*>(o1b + n * 256 + k4 * 4);
                acc[n] += wc.x * hv.x + wc.y * hv.y + wc.z * hv.z + wc.w * hv.w;
            }
        }
#pragma unroll
        for (int n = 0; n < 32; n++) sH[n * 256 + tid] = acc[n];
        sB2[tid] = bacc;
    }
    __syncthreads();
    for (int e = tid; e < 4096; e += 256) {
        int n = e >> 7, o2 = e & 127;
        float v = sH[n * 256 + o2] + sH[n * 256 + o2 + 128];
        float base = s2_lb[o2] + (sB2[o2] + sB2[o2 + 128]) * (1.f / 31.f);
        out[(b * 32 + n) * 128 + o2] = base + v;
    }
}

// ---------------- launch ----------------
extern "C" void kernel_launch(void* const* d_in, const int* in_sizes, int n_in,
                              void* d_out, int out_size) {
    const float* x       = (const float*)d_in[0];
    const float* mask    = (const float*)d_in[1];
    const float* conv1_w = (const float*)d_in[2];
    const float* conv1_b = (const float*)d_in[3];
    const float* conv2_w = (const float*)d_in[4];
    const float* conv2_b = (const float*)d_in[5];
    const float* fc_w    = (const float*)d_in[6];
    const float* fc_b    = (const float*)d_in[7];
    const float* s1_lw   = (const float*)d_in[8];
    const float* s1_lb   = (const float*)d_in[9];
    const float* s1_rw   = (const float*)d_in[10];
    const float* s2_lw   = (const float*)d_in[11];
    const float* s2_lb   = (const float*)d_in[12];
    const float* s2_rw   = (const float*)d_in[13];
    float* out = (float*)d_out;

    cudaFuncSetAttribute(conv_fused_kernel, cudaFuncAttributeMaxDynamicSharedMemorySize,
                         SMEM2_TOTAL);
    cudaFuncSetAttribute(tail_kernel, cudaFuncAttributeMaxDynamicSharedMemorySize, TAIL_SMEM);

    conv_fused_kernel<<<148, 512, SMEM2_TOTAL>>>(x, conv1_w, conv1_b, conv2_w, conv2_b);
    tail_kernel<<<32, 256, TAIL_SMEM>>>(fc_w, fc_b, mask, s1_lw, s1_lb, s1_rw,
                                        s2_lw, s2_lb, s2_rw, out);
}